// round 2
// baseline (speedup 1.0000x reference)
#include <cuda_runtime.h>
#include <cstdint>
#include <math.h>

#define BATCH 128
#define TT    1024
#define FF    128
#define KK    32

// Scratch (device globals: allocation-free per harness rules)
static __device__ float  g_eem[(size_t)BATCH * TT * KK];   // exp(em - rowmax), 67MB
static __device__ float  g_c[(size_t)BATCH * TT];          // rowmax of emission
static __device__ double g_partial[BATCH];

// ---------- packed f32x2 helpers (Blackwell FFMA2 path) ----------
__device__ __forceinline__ unsigned long long pack2(float lo, float hi) {
    unsigned long long r;
    asm("mov.b64 %0, {%1, %2};" : "=l"(r) : "f"(lo), "f"(hi));
    return r;
}
__device__ __forceinline__ void unpack2(unsigned long long v, float& lo, float& hi) {
    asm("mov.b64 {%0, %1}, %2;" : "=f"(lo), "=f"(hi) : "l"(v));
}
__device__ __forceinline__ unsigned long long fma2(unsigned long long a,
                                                   unsigned long long b,
                                                   unsigned long long c) {
    unsigned long long d;
    asm("fma.rn.f32x2 %0, %1, %2, %3;" : "=l"(d) : "l"(a), "l"(b), "l"(c));
    return d;
}

// =====================================================================
// Kernel 1: emission GEMM + row-max + exp.
//   em[row][k] = sum_f x[row][f] * W[f][k];  c = max_k em;  eem = exp(em - c)
// Block: 256 threads, tile 128 rows x 32 cols. tx(0..7) -> 4 cols, ty(0..31) -> 4 rows.
// =====================================================================
__global__ __launch_bounds__(256) void emis_kernel(const float* __restrict__ x,
                                                   const float* __restrict__ W) {
    __shared__ float Ws[FF * KK];     // [f][k]
    __shared__ float Xs[32 * 132];    // [ff][r], padded stride 132 (conflict-free reads)

    const int tid = threadIdx.x;
    const int tx = tid & 7;           // col group (4 cols)
    const int ty = tid >> 3;          // row group (4 rows)
    const int c0 = tx * 4;
    const int row0 = blockIdx.x * 128;

    // Load full W once (4096 floats)
    #pragma unroll
    for (int i = 0; i < 16; i++) Ws[tid + i * 256] = W[tid + i * 256];

    unsigned long long acc01[4], acc23[4];
    #pragma unroll
    for (int i = 0; i < 4; i++) { acc01[i] = 0ull; acc23[i] = 0ull; }  // {0.f,0.f}

    for (int ch = 0; ch < 4; ch++) {
        __syncthreads();
        // Stage X chunk: 128 rows x 32 f -> Xs[ff][r]
        #pragma unroll
        for (int it = 0; it < 16; it++) {
            int l = it * 256 + tid;           // 0..4095
            int r = l >> 5, ff = l & 31;
            Xs[ff * 132 + r] = x[(size_t)(row0 + r) * FF + ch * 32 + ff];
        }
        __syncthreads();

        #pragma unroll
        for (int ff = 0; ff < 32; ff++) {
            const float2 wa = *(const float2*)&Ws[(ch * 32 + ff) * KK + c0];
            const float2 wb = *(const float2*)&Ws[(ch * 32 + ff) * KK + c0 + 2];
            const unsigned long long w01 = pack2(wa.x, wa.y);
            const unsigned long long w23 = pack2(wb.x, wb.y);
            #pragma unroll
            for (int i = 0; i < 4; i++) {
                float xv = Xs[ff * 132 + ty * 4 + i];     // broadcast across tx
                unsigned long long xx = pack2(xv, xv);
                acc01[i] = fma2(xx, w01, acc01[i]);
                acc23[i] = fma2(xx, w23, acc23[i]);
            }
        }
    }

    // Epilogue: per-row max across 32 cols (local 4 + shfl over tx), then exp
    #pragma unroll
    for (int i = 0; i < 4; i++) {
        float e0, e1, e2, e3;
        unpack2(acc01[i], e0, e1);
        unpack2(acc23[i], e2, e3);
        float m = fmaxf(fmaxf(e0, e1), fmaxf(e2, e3));
        m = fmaxf(m, __shfl_xor_sync(0xffffffffu, m, 1));
        m = fmaxf(m, __shfl_xor_sync(0xffffffffu, m, 2));
        m = fmaxf(m, __shfl_xor_sync(0xffffffffu, m, 4));
        const int row = row0 + ty * 4 + i;
        float4 outv;
        outv.x = __expf(e0 - m);
        outv.y = __expf(e1 - m);
        outv.z = __expf(e2 - m);
        outv.w = __expf(e3 - m);
        *(float4*)&g_eem[(size_t)row * KK + c0] = outv;
        if (tx == 0) g_c[row] = m;
    }
}

// =====================================================================
// Kernel 2: linear-space forward scan. One warp per batch; lane = state k.
//   a_t[k] = (sum_j a_{t-1}[j] * expT[j][k]) * eem[t][k], offset o += c_t (if mask)
// =====================================================================
__device__ __forceinline__ void crf_step(float& a, double& o,
                                         const float (&r)[32],
                                         float e, float ct, int m) {
    float acc0 = 0.f, acc1 = 0.f, acc2 = 0.f, acc3 = 0.f;
    float acc4 = 0.f, acc5 = 0.f, acc6 = 0.f, acc7 = 0.f;
    #pragma unroll
    for (int j = 0; j < 32; j += 8) {
        acc0 = fmaf(__shfl_sync(0xffffffffu, a, j + 0), r[j + 0], acc0);
        acc1 = fmaf(__shfl_sync(0xffffffffu, a, j + 1), r[j + 1], acc1);
        acc2 = fmaf(__shfl_sync(0xffffffffu, a, j + 2), r[j + 2], acc2);
        acc3 = fmaf(__shfl_sync(0xffffffffu, a, j + 3), r[j + 3], acc3);
        acc4 = fmaf(__shfl_sync(0xffffffffu, a, j + 4), r[j + 4], acc4);
        acc5 = fmaf(__shfl_sync(0xffffffffu, a, j + 5), r[j + 5], acc5);
        acc6 = fmaf(__shfl_sync(0xffffffffu, a, j + 6), r[j + 6], acc6);
        acc7 = fmaf(__shfl_sync(0xffffffffu, a, j + 7), r[j + 7], acc7);
    }
    float s = ((acc0 + acc1) + (acc2 + acc3)) + ((acc4 + acc5) + (acc6 + acc7));
    float an = s * e;
    if (m) { a = an; o += (double)ct; }
}

__device__ __forceinline__ void renorm(float& a, double& o) {
    float mx = a;
    #pragma unroll
    for (int off = 1; off < 32; off <<= 1)
        mx = fmaxf(mx, __shfl_xor_sync(0xffffffffu, mx, off));
    int ei;
    frexpf(mx, &ei);                               // mx = f * 2^ei, f in [0.5,1)
    float sc = __int_as_float((127 - ei) << 23);   // exact 2^-ei
    a *= sc;
    o += (double)ei * 0.6931471805599453;
}

__global__ __launch_bounds__(32) void scan_kernel(const int* __restrict__ mask,
                                                  const float* __restrict__ trans) {
    const int b = blockIdx.x;
    const int k = threadIdx.x;

    // expT column k in registers (double-precision exp once, negligible cost)
    float r[32];
    #pragma unroll
    for (int j = 0; j < 32; j++)
        r[j] = (float)exp((double)trans[j * KK + k]);

    const float* eemb = g_eem + (size_t)b * TT * KK;
    const float* cb   = g_c   + (size_t)b * TT;
    const int*   mb   = mask + (size_t)b * TT;

    float  a = eemb[k];     // t = 0: alpha0 = em0 -> a = exp(em0 - c0)
    double o = (double)cb[0];

    // Software-pipelined chunks of 8 steps: preload next chunk while computing current
    float eCur[8], cCur[8];
    int mCur[8];
    #pragma unroll
    for (int i = 0; i < 8; i++) {
        eCur[i] = eemb[(1 + i) * KK + k];
        cCur[i] = cb[1 + i];
        mCur[i] = mb[1 + i];
    }

    int t = 1;
    for (int chunk = 0; chunk < 127; chunk++, t += 8) {   // t = 1..1016
        float eNxt[8], cNxt[8];
        int mNxt[8];
        if (chunk < 126) {
            const int tn = t + 8;
            #pragma unroll
            for (int i = 0; i < 8; i++) {
                eNxt[i] = eemb[(tn + i) * KK + k];
                cNxt[i] = cb[tn + i];
                mNxt[i] = mb[tn + i];
            }
        } else {
            #pragma unroll
            for (int i = 0; i < 8; i++) { eNxt[i] = 0.f; cNxt[i] = 0.f; mNxt[i] = 0; }
        }

        #pragma unroll
        for (int i = 0; i < 8; i++)
            crf_step(a, o, r, eCur[i], cCur[i], mCur[i]);

        if (chunk & 1) renorm(a, o);                       // every 16 steps

        #pragma unroll
        for (int i = 0; i < 8; i++) {
            eCur[i] = eNxt[i]; cCur[i] = cNxt[i]; mCur[i] = mNxt[i];
        }
    }

    // Remainder: t = 1017..1023
    for (; t < TT; t++) {
        float e  = eemb[t * KK + k];
        float ct = cb[t];
        int   m  = mb[t];
        crf_step(a, o, r, e, ct, m);
    }

    // log_z = o + log(sum_k a_k)
    float s = a;
    #pragma unroll
    for (int off = 1; off < 32; off <<= 1)
        s += __shfl_xor_sync(0xffffffffu, s, off);
    double lz = o + (double)__logf(s);
    if (k == 0) g_partial[b] = lz;
}

// =====================================================================
// Kernel 3: deterministic reduction of 128 per-batch log_z values
// =====================================================================
__global__ __launch_bounds__(128) void reduce_kernel(float* __restrict__ out) {
    __shared__ double ws[4];
    const int t = threadIdx.x;
    double v = g_partial[t];
    #pragma unroll
    for (int off = 16; off > 0; off >>= 1)
        v += __shfl_xor_sync(0xffffffffu, v, off);
    if ((t & 31) == 0) ws[t >> 5] = v;
    __syncthreads();
    if (t == 0) out[0] = (float)(ws[0] + ws[1] + ws[2] + ws[3]);
}

extern "C" void kernel_launch(void* const* d_in, const int* in_sizes, int n_in,
                              void* d_out, int out_size) {
    const float* x     = (const float*)d_in[0];
    const int*   mask  = (const int*)d_in[1];
    const float* W     = (const float*)d_in[2];
    const float* trans = (const float*)d_in[3];

    emis_kernel<<<(BATCH * TT) / 128, 256>>>(x, W);
    scan_kernel<<<BATCH, 32>>>(mask, trans);
    reduce_kernel<<<1, 128>>>((float*)d_out);
}

// round 3
// speedup vs baseline: 3.3809x; 3.3809x over previous
#include <cuda_runtime.h>
#include <cstdint>
#include <math.h>

#define BATCH 128
#define TT    1024
#define FF    128
#define KK    32
#define NCH   16      // chunks per batch
#define CLEN  64      // steps per chunk
#define WARM  32      // warmup steps

// Scratch (device globals: allocation-free per harness rules)
static __device__ float g_eem[(size_t)BATCH * TT * KK];   // exp(em), 16MB
static __device__ float g_part[BATCH * NCH];              // per-(batch,chunk) D

// ---------- packed f32x2 helpers ----------
__device__ __forceinline__ unsigned long long pack2(float lo, float hi) {
    unsigned long long r;
    asm("mov.b64 %0, {%1, %2};" : "=l"(r) : "f"(lo), "f"(hi));
    return r;
}
__device__ __forceinline__ void unpack2(unsigned long long v, float& lo, float& hi) {
    asm("mov.b64 {%0, %1}, %2;" : "=f"(lo), "=f"(hi) : "l"(v));
}
__device__ __forceinline__ unsigned long long fma2(unsigned long long a,
                                                   unsigned long long b,
                                                   unsigned long long c) {
    unsigned long long d;
    asm("fma.rn.f32x2 %0, %1, %2, %3;" : "=l"(d) : "l"(a), "l"(b), "l"(c));
    return d;
}

// =====================================================================
// Kernel 1: emission GEMM + exp.  eem[row][k] = exp(sum_f x[row][f]*W[f][k])
// Block 256 threads, tile 256 rows x 32 cols; thread: 8 rows x 4 cols.
// =====================================================================
__device__ __forceinline__ int xidx(int ff, int rr) {
    // [rr][ff] with per-row rotate: bank = (rr+ff)%32, broadcast-safe reads
    return rr * 32 + ((ff + rr) & 31);
}

__global__ __launch_bounds__(256) void emis_kernel(const float* __restrict__ x,
                                                   const float* __restrict__ W) {
    __shared__ float Ws[FF * KK];      // 16KB, [f][k]
    __shared__ float Xs[256 * 32];     // 32KB, rotate-swizzled

    const int tid = threadIdx.x;
    const int tx = tid & 7;            // col group (4 cols)
    const int ty = tid >> 3;           // row group (8 rows)
    const int c0 = tx * 4;
    const int row0 = blockIdx.x * 256;

    #pragma unroll
    for (int i = 0; i < 16; i++) Ws[tid + i * 256] = W[tid + i * 256];

    unsigned long long acc01[8], acc23[8];
    #pragma unroll
    for (int i = 0; i < 8; i++) { acc01[i] = 0ull; acc23[i] = 0ull; }

    for (int ch = 0; ch < 4; ch++) {
        __syncthreads();
        // Stage 256 rows x 32 ff
        #pragma unroll
        for (int it = 0; it < 32; it++) {
            int l = it * 256 + tid;            // 0..8191
            int ff = l & 31, rr = l >> 5;
            Xs[xidx(ff, rr)] = x[(size_t)(row0 + rr) * FF + ch * 32 + ff];
        }
        __syncthreads();

        #pragma unroll
        for (int ff = 0; ff < 32; ff++) {
            const float4 w = *(const float4*)&Ws[(ch * 32 + ff) * KK + c0];
            const unsigned long long w01 = pack2(w.x, w.y);
            const unsigned long long w23 = pack2(w.z, w.w);
            #pragma unroll
            for (int i = 0; i < 8; i++) {
                float xv = Xs[xidx(ff, ty * 8 + i)];   // broadcast across tx
                unsigned long long xx = pack2(xv, xv);
                acc01[i] = fma2(xx, w01, acc01[i]);
                acc23[i] = fma2(xx, w23, acc23[i]);
            }
        }
    }

    #pragma unroll
    for (int i = 0; i < 8; i++) {
        float e0, e1, e2, e3;
        unpack2(acc01[i], e0, e1);
        unpack2(acc23[i], e2, e3);
        const int row = row0 + ty * 8 + i;
        float4 outv;
        outv.x = __expf(e0);
        outv.y = __expf(e1);
        outv.z = __expf(e2);
        outv.w = __expf(e3);
        *(float4*)&g_eem[(size_t)row * KK + c0] = outv;
    }
}

// =====================================================================
// Kernel 2: chunked linear-space forward scan with warmup (Birkhoff
// contraction makes the direction forget its init in ~32 steps).
// One warp per (batch, chunk); lane = state k.
// =====================================================================
__device__ __forceinline__ void crf_step(float& a, const float (&r)[32],
                                         float e, int m) {
    float x = a;
    float a0 = __shfl_sync(0xffffffffu, x, 0) * r[0];
    float a1 = __shfl_sync(0xffffffffu, x, 1) * r[1];
    float a2 = __shfl_sync(0xffffffffu, x, 2) * r[2];
    float a3 = __shfl_sync(0xffffffffu, x, 3) * r[3];
    float a4 = __shfl_sync(0xffffffffu, x, 4) * r[4];
    float a5 = __shfl_sync(0xffffffffu, x, 5) * r[5];
    float a6 = __shfl_sync(0xffffffffu, x, 6) * r[6];
    float a7 = __shfl_sync(0xffffffffu, x, 7) * r[7];
    #pragma unroll
    for (int j = 8; j < 32; j += 8) {
        a0 = fmaf(__shfl_sync(0xffffffffu, x, j + 0), r[j + 0], a0);
        a1 = fmaf(__shfl_sync(0xffffffffu, x, j + 1), r[j + 1], a1);
        a2 = fmaf(__shfl_sync(0xffffffffu, x, j + 2), r[j + 2], a2);
        a3 = fmaf(__shfl_sync(0xffffffffu, x, j + 3), r[j + 3], a3);
        a4 = fmaf(__shfl_sync(0xffffffffu, x, j + 4), r[j + 4], a4);
        a5 = fmaf(__shfl_sync(0xffffffffu, x, j + 5), r[j + 5], a5);
        a6 = fmaf(__shfl_sync(0xffffffffu, x, j + 6), r[j + 6], a6);
        a7 = fmaf(__shfl_sync(0xffffffffu, x, j + 7), r[j + 7], a7);
    }
    float s = ((a0 + a1) + (a2 + a3)) + ((a4 + a5) + (a6 + a7));
    float an = s * e;
    a = m ? an : a;
}

__device__ __forceinline__ void renorm(float& a, int& oexp) {
    float mx = a;
    #pragma unroll
    for (int off = 16; off > 0; off >>= 1)
        mx = fmaxf(mx, __shfl_xor_sync(0xffffffffu, mx, off));
    int ei = (__float_as_int(mx) >> 23) & 255;    // biased exponent
    oexp += ei - 127;
    a *= __int_as_float((254 - ei) << 23);        // exact 2^(127-ei)
}

__device__ __forceinline__ float bsum(float a) {
    float s = a;
    #pragma unroll
    for (int off = 16; off > 0; off >>= 1)
        s += __shfl_xor_sync(0xffffffffu, s, off);
    return s;
}

__device__ __forceinline__ void run_span(float& a, const float (&r)[32],
                                         const float* __restrict__ eemb,
                                         const int* __restrict__ mb,
                                         int t, int tend, int k, int& oexp) {
    float eA[8]; int mA[8];
    if (t + 8 <= tend) {
        #pragma unroll
        for (int i = 0; i < 8; i++) { eA[i] = eemb[(t + i) * KK + k]; mA[i] = mb[t + i]; }
    }
    while (t + 8 <= tend) {
        float eB[8]; int mB[8];
        const bool more = (t + 16 <= tend);
        if (more) {
            #pragma unroll
            for (int i = 0; i < 8; i++) { eB[i] = eemb[(t + 8 + i) * KK + k]; mB[i] = mb[t + 8 + i]; }
        } else {
            #pragma unroll
            for (int i = 0; i < 8; i++) { eB[i] = 0.f; mB[i] = 0; }
        }
        #pragma unroll
        for (int i = 0; i < 8; i++) crf_step(a, r, eA[i], mA[i]);
        renorm(a, oexp);
        #pragma unroll
        for (int i = 0; i < 8; i++) { eA[i] = eB[i]; mA[i] = mB[i]; }
        t += 8;
    }
    for (; t < tend; t++)
        crf_step(a, r, eemb[t * KK + k], mb[t]);
}

__global__ __launch_bounds__(32) void scan_kernel(const int* __restrict__ mask,
                                                  const float* __restrict__ trans) {
    const int b = blockIdx.x >> 4;     // / NCH
    const int c = blockIdx.x & (NCH - 1);
    const int k = threadIdx.x;

    float r[32];                        // expT column k
    #pragma unroll
    for (int j = 0; j < 32; j++)
        r[j] = expf(trans[j * KK + k]);

    const float* eemb = g_eem + (size_t)b * TT * KK;
    const int*   mb   = mask + (size_t)b * TT;

    float a, m0 = 0.f;
    int oexp = 0, dummy = 0;

    if (c == 0) {
        a = eemb[k];                              // alpha0 = em0 (exp form)
        run_span(a, r, eemb, mb, 1, CLEN, k, oexp);
    } else {
        a = 1.f;                                  // uniform init, forgotten by warmup
        const int ts = c * CLEN;
        run_span(a, r, eemb, mb, ts - WARM, ts, k, dummy);   // warmup
        m0 = logf(bsum(a));
        run_span(a, r, eemb, mb, ts, ts + CLEN, k, oexp);    // measured
    }

    float D = (float)oexp * 0.69314718055994531f + logf(bsum(a)) - m0;
    if (k == 0) g_part[blockIdx.x] = D;
}

// =====================================================================
// Kernel 3: deterministic reduction of 2048 chunk contributions
// =====================================================================
__global__ __launch_bounds__(256) void reduce_kernel(float* __restrict__ out) {
    __shared__ double ws[8];
    const int t = threadIdx.x;
    double v = 0.0;
    #pragma unroll
    for (int i = 0; i < 8; i++) v += (double)g_part[t * 8 + i];
    #pragma unroll
    for (int off = 16; off > 0; off >>= 1)
        v += __shfl_xor_sync(0xffffffffu, v, off);
    if ((t & 31) == 0) ws[t >> 5] = v;
    __syncthreads();
    if (t == 0) {
        double s = 0.0;
        #pragma unroll
        for (int i = 0; i < 8; i++) s += ws[i];
        out[0] = (float)s;
    }
}

extern "C" void kernel_launch(void* const* d_in, const int* in_sizes, int n_in,
                              void* d_out, int out_size) {
    const float* x     = (const float*)d_in[0];
    const int*   mask  = (const int*)d_in[1];
    const float* W     = (const float*)d_in[2];
    const float* trans = (const float*)d_in[3];

    emis_kernel<<<(BATCH * TT) / 256, 256>>>(x, W);
    scan_kernel<<<BATCH * NCH, 32>>>(mask, trans);
    reduce_kernel<<<1, 256>>>((float*)d_out);
}

// round 5
// speedup vs baseline: 4.2038x; 1.2434x over previous
#include <cuda_runtime.h>
#include <cstdint>
#include <math.h>

#define BATCH 128
#define TT    1024
#define FF    128
#define KK    32
#define NCH   16      // chunks per batch
#define CLEN  64      // steps per chunk
#define WARM  32      // warmup steps

// Scratch (device globals: allocation-free per harness rules)
static __device__ float g_eem[(size_t)BATCH * TT * KK];   // exp(em), 16MB
static __device__ float g_part[BATCH * NCH];              // per-(batch,chunk) D

// ---------- packed f32x2 helpers (FFMA2 path) ----------
__device__ __forceinline__ unsigned long long pack2(float lo, float hi) {
    unsigned long long r;
    asm("mov.b64 %0, {%1, %2};" : "=l"(r) : "f"(lo), "f"(hi));
    return r;
}
__device__ __forceinline__ void unpack2(unsigned long long v, float& lo, float& hi) {
    asm("mov.b64 {%0, %1}, %2;" : "=f"(lo), "=f"(hi) : "l"(v));
}
__device__ __forceinline__ unsigned long long fma2(unsigned long long a,
                                                   unsigned long long b,
                                                   unsigned long long c) {
    unsigned long long d;
    asm("fma.rn.f32x2 %0, %1, %2, %3;" : "=l"(d) : "l"(a), "l"(b), "l"(c));
    return d;
}

// fast exp on the FMA pipe (rel err ~4e-5 over |x|<~3); avoids the MUFU floor
__device__ __forceinline__ float fast_exp(float x) {
    float t = x * 1.4426950408889634f;
    float n = rintf(t);
    float f = t - n;
    float p = 0.0096853f;
    p = fmaf(p, f, 0.05550411f);
    p = fmaf(p, f, 0.24022651f);
    p = fmaf(p, f, 0.69314718f);
    p = fmaf(p, f, 1.0f);
    return __int_as_float(__float_as_int(p) + (((int)n) << 23));
}

// =====================================================================
// Kernel 1: emission GEMM + exp.  eem[row][k] = exp(sum_f x[row][f]*W[f][k])
// Block 256 threads, tile 128 rows x 32 cols; thread: 4 rows x 4 cols.
// Inner loop per ff: 2x LDS.128 + 8 FFMA2 (FMA-bound by design).
// =====================================================================
#define XS_STRIDE 132   // multiple of 4 (aligned float4 reads), bank offset 4/row

__global__ __launch_bounds__(256) void emis_kernel(const float* __restrict__ x,
                                                   const float* __restrict__ W) {
    __shared__ float Ws[FF * KK];            // 16KB, [f][k]
    __shared__ float Xs[32 * XS_STRIDE];     // ~17KB, [ff][row]

    const int tid = threadIdx.x;
    const int tx = tid & 7;                  // col group (4 cols)
    const int ty = tid >> 3;                 // row group (4 rows)
    const int c0 = tx * 4;
    const int row0 = blockIdx.x * 128;

    // Load full W (4096 floats) via float4
    {
        const float4* Wv = reinterpret_cast<const float4*>(W);
        float4* Wsv = reinterpret_cast<float4*>(Ws);
        #pragma unroll
        for (int i = 0; i < 4; i++) Wsv[tid + i * 256] = Wv[tid + i * 256];
    }

    unsigned long long acc01[4], acc23[4];
    #pragma unroll
    for (int i = 0; i < 4; i++) { acc01[i] = 0ull; acc23[i] = 0ull; }

    for (int ch = 0; ch < 4; ch++) {
        __syncthreads();
        // Stage 128 rows x 32 ff chunk via float4 loads (1024 float4, 4/thread)
        #pragma unroll
        for (int it = 0; it < 4; it++) {
            int idx = it * 256 + tid;        // 0..1023
            int r = idx >> 3, q = idx & 7;   // row, float4-within-chunk
            float4 v = *reinterpret_cast<const float4*>(
                x + (size_t)(row0 + r) * FF + ch * 32 + q * 4);
            Xs[(q * 4 + 0) * XS_STRIDE + r] = v.x;
            Xs[(q * 4 + 1) * XS_STRIDE + r] = v.y;
            Xs[(q * 4 + 2) * XS_STRIDE + r] = v.z;
            Xs[(q * 4 + 3) * XS_STRIDE + r] = v.w;
        }
        __syncthreads();

        #pragma unroll
        for (int ff = 0; ff < 32; ff++) {
            const float4 w = *(const float4*)&Ws[(ch * 32 + ff) * KK + c0];
            const unsigned long long w01 = pack2(w.x, w.y);
            const unsigned long long w23 = pack2(w.z, w.w);
            const float4 xv = *(const float4*)&Xs[ff * XS_STRIDE + ty * 4];
            acc01[0] = fma2(pack2(xv.x, xv.x), w01, acc01[0]);
            acc23[0] = fma2(pack2(xv.x, xv.x), w23, acc23[0]);
            acc01[1] = fma2(pack2(xv.y, xv.y), w01, acc01[1]);
            acc23[1] = fma2(pack2(xv.y, xv.y), w23, acc23[1]);
            acc01[2] = fma2(pack2(xv.z, xv.z), w01, acc01[2]);
            acc23[2] = fma2(pack2(xv.z, xv.z), w23, acc23[2]);
            acc01[3] = fma2(pack2(xv.w, xv.w), w01, acc01[3]);
            acc23[3] = fma2(pack2(xv.w, xv.w), w23, acc23[3]);
        }
    }

    // Epilogue: exp on FMA pipe, vectorized store
    #pragma unroll
    for (int i = 0; i < 4; i++) {
        float e0, e1, e2, e3;
        unpack2(acc01[i], e0, e1);
        unpack2(acc23[i], e2, e3);
        const int row = row0 + ty * 4 + i;
        float4 o;
        o.x = fast_exp(e0);
        o.y = fast_exp(e1);
        o.z = fast_exp(e2);
        o.w = fast_exp(e3);
        *(float4*)&g_eem[(size_t)row * KK + c0] = o;
    }
}

// =====================================================================
// Kernel 2: chunked linear-space forward scan (Birkhoff contraction
// warmup). One warp per (batch, chunk); lane = state k.
// alpha broadcast via double-buffered smem (1 STS + 8 LDS.128 per step
// instead of 32 shfls — crossbar was the R3 bottleneck).
// =====================================================================
__device__ __forceinline__ void crf_step(float& a, const float (&r)[32],
                                         float* sbuf, float e, int m,
                                         int k, int ph) {
    float* b = sbuf + (ph << 5);
    b[k] = a;
    __syncwarp();
    const float4* v = reinterpret_cast<const float4*>(b);
    float4 v0 = v[0], v1 = v[1], v2 = v[2], v3 = v[3];
    float4 v4 = v[4], v5 = v[5], v6 = v[6], v7 = v[7];
    float s0 = v0.x * r[0];  s0 = fmaf(v0.y, r[1],  s0); s0 = fmaf(v0.z, r[2],  s0); s0 = fmaf(v0.w, r[3],  s0);
    float s1 = v1.x * r[4];  s1 = fmaf(v1.y, r[5],  s1); s1 = fmaf(v1.z, r[6],  s1); s1 = fmaf(v1.w, r[7],  s1);
    float s2 = v2.x * r[8];  s2 = fmaf(v2.y, r[9],  s2); s2 = fmaf(v2.z, r[10], s2); s2 = fmaf(v2.w, r[11], s2);
    float s3 = v3.x * r[12]; s3 = fmaf(v3.y, r[13], s3); s3 = fmaf(v3.z, r[14], s3); s3 = fmaf(v3.w, r[15], s3);
    float s4 = v4.x * r[16]; s4 = fmaf(v4.y, r[17], s4); s4 = fmaf(v4.z, r[18], s4); s4 = fmaf(v4.w, r[19], s4);
    float s5 = v5.x * r[20]; s5 = fmaf(v5.y, r[21], s5); s5 = fmaf(v5.z, r[22], s5); s5 = fmaf(v5.w, r[23], s5);
    float s6 = v6.x * r[24]; s6 = fmaf(v6.y, r[25], s6); s6 = fmaf(v6.z, r[26], s6); s6 = fmaf(v6.w, r[27], s6);
    float s7 = v7.x * r[28]; s7 = fmaf(v7.y, r[29], s7); s7 = fmaf(v7.z, r[30], s7); s7 = fmaf(v7.w, r[31], s7);
    float s = ((s0 + s1) + (s2 + s3)) + ((s4 + s5) + (s6 + s7));
    a = m ? s * e : a;
}

__device__ __forceinline__ void renorm(float& a, int& oexp) {
    float mx = a;
    #pragma unroll
    for (int off = 16; off > 0; off >>= 1)
        mx = fmaxf(mx, __shfl_xor_sync(0xffffffffu, mx, off));
    int ei = (__float_as_int(mx) >> 23) & 255;
    oexp += ei - 127;
    a *= __int_as_float((254 - ei) << 23);     // exact 2^(127-ei)
}

__device__ __forceinline__ float bsum(float a) {
    float s = a;
    #pragma unroll
    for (int off = 16; off > 0; off >>= 1)
        s += __shfl_xor_sync(0xffffffffu, s, off);
    return s;
}

__device__ __forceinline__ void run_span(float& a, const float (&r)[32],
                                         float* sbuf,
                                         const float* __restrict__ eemb,
                                         const int* __restrict__ mb,
                                         int t, int tend, int k, int& oexp) {
    float eA[8]; int mA[8];
    if (t + 8 <= tend) {
        #pragma unroll
        for (int i = 0; i < 8; i++) { eA[i] = eemb[(t + i) * KK + k]; mA[i] = mb[t + i]; }
    }
    while (t + 8 <= tend) {
        float eB[8]; int mB[8];
        if (t + 16 <= tend) {
            #pragma unroll
            for (int i = 0; i < 8; i++) { eB[i] = eemb[(t + 8 + i) * KK + k]; mB[i] = mb[t + 8 + i]; }
        } else {
            #pragma unroll
            for (int i = 0; i < 8; i++) { eB[i] = 0.f; mB[i] = 0; }
        }
        #pragma unroll
        for (int i = 0; i < 8; i++) crf_step(a, r, sbuf, eA[i], mA[i], k, (t + i) & 1);
        renorm(a, oexp);
        #pragma unroll
        for (int i = 0; i < 8; i++) { eA[i] = eB[i]; mA[i] = mB[i]; }
        t += 8;
    }
    for (; t < tend; t++)
        crf_step(a, r, sbuf, eemb[t * KK + k], mb[t], k, t & 1);
}

__global__ __launch_bounds__(32) void scan_kernel(const int* __restrict__ mask,
                                                  const float* __restrict__ trans) {
    __shared__ __align__(16) float sbuf[64];   // double-buffered alpha broadcast
    const int b = blockIdx.x >> 4;             // / NCH
    const int c = blockIdx.x & (NCH - 1);
    const int k = threadIdx.x;

    float r[32];                               // expT column k
    #pragma unroll
    for (int j = 0; j < 32; j++)
        r[j] = expf(trans[j * KK + k]);

    const float* eemb = g_eem + (size_t)b * TT * KK;
    const int*   mb   = mask + (size_t)b * TT;

    float a, m0 = 0.f;
    int oexp = 0, dummy = 0;

    if (c == 0) {
        a = eemb[k];                           // alpha0 = em0 (exp form)
        run_span(a, r, sbuf, eemb, mb, 1, CLEN, k, oexp);
    } else {
        a = 1.f;                               // uniform init, forgotten by warmup
        const int ts = c * CLEN;
        run_span(a, r, sbuf, eemb, mb, ts - WARM, ts, k, dummy);
        m0 = logf(bsum(a));
        run_span(a, r, sbuf, eemb, mb, ts, ts + CLEN, k, oexp);
    }

    float D = (float)oexp * 0.69314718055994531f + logf(bsum(a)) - m0;
    if (k == 0) g_part[blockIdx.x] = D;
}

// =====================================================================
// Kernel 3: deterministic reduction of 2048 chunk contributions
// =====================================================================
__global__ __launch_bounds__(256) void reduce_kernel(float* __restrict__ out) {
    __shared__ double ws[8];
    const int t = threadIdx.x;
    double v = 0.0;
    #pragma unroll
    for (int i = 0; i < 8; i++) v += (double)g_part[t * 8 + i];
    #pragma unroll
    for (int off = 16; off > 0; off >>= 1)
        v += __shfl_xor_sync(0xffffffffu, v, off);
    if ((t & 31) == 0) ws[t >> 5] = v;
    __syncthreads();
    if (t == 0) {
        double s = 0.0;
        #pragma unroll
        for (int i = 0; i < 8; i++) s += ws[i];
        out[0] = (float)s;
    }
}

extern "C" void kernel_launch(void* const* d_in, const int* in_sizes, int n_in,
                              void* d_out, int out_size) {
    const float* x     = (const float*)d_in[0];
    const int*   mask  = (const int*)d_in[1];
    const float* W     = (const float*)d_in[2];
    const float* trans = (const float*)d_in[3];

    emis_kernel<<<(BATCH * TT) / 128, 256>>>(x, W);
    scan_kernel<<<BATCH * NCH, 32>>>(mask, trans);
    reduce_kernel<<<1, 256>>>((float*)d_out);
}

// round 6
// speedup vs baseline: 5.5636x; 1.3235x over previous
#include <cuda_runtime.h>
#include <cstdint>
#include <math.h>

#define BATCH 128
#define TT    1024
#define FF    128
#define KK    32
#define NCH   16      // chunks per batch
#define CLEN  64      // steps per chunk
#define WARM  32      // warmup steps

// Scratch (device globals: allocation-free per harness rules)
static __device__ float g_eem[(size_t)BATCH * TT * KK];   // exp(em), 16MB
static __device__ float g_part[BATCH * NCH];              // per-(batch,chunk) D

// fast exp on the FMA pipe (rel err ~4e-5 over |x|<~3); avoids the MUFU floor
__device__ __forceinline__ float fast_exp(float x) {
    float t = x * 1.4426950408889634f;
    float n = rintf(t);
    float f = t - n;
    float p = 0.0096853f;
    p = fmaf(p, f, 0.05550411f);
    p = fmaf(p, f, 0.24022651f);
    p = fmaf(p, f, 0.69314718f);
    p = fmaf(p, f, 1.0f);
    return __int_as_float(__float_as_int(p) + (((int)n) << 23));
}

// =====================================================================
// Kernel 1: emission GEMM on mma.sync tf32 + fast exp.
//   eem[row][k] = exp(sum_f x[row][f] * W[f][k])
// CTA: 128 threads (4 warps), tile 128 rows x 32 states, K=128 in 4 chunks.
// Warp w owns rows w*32..w*32+31 (2 m16 tiles x 4 n8 tiles).
// Raw fp32 bits fed as tf32 (truncation; ~3e-5 abs err on em).
// =====================================================================
#define XST 36   // Xs row stride (words): LDS bank = (4g + c) -> conflict-free frags
#define WST 40   // Wsm row stride (words): LDS bank = (8*c4 + g) -> conflict-free

__global__ __launch_bounds__(128) void emis_mma(const float* __restrict__ x,
                                                const float* __restrict__ W) {
    __shared__ __align__(16) float Xs[128 * XST];   // 18.4KB
    __shared__ __align__(16) float Wsm[128 * WST];  // 20.5KB

    const int tid  = threadIdx.x;
    const int lane = tid & 31;
    const int w    = tid >> 5;
    const int g    = lane >> 2;      // 0..7
    const int c4   = lane & 3;       // 0..3
    const int row0 = blockIdx.x * 128;

    // Stage all of W: [f][n] at stride WST
    #pragma unroll
    for (int i = 0; i < 32; i++) {
        int idx = i * 128 + tid;
        Wsm[(idx >> 5) * WST + (idx & 31)] = W[idx];
    }

    float d[2][4][4];
    #pragma unroll
    for (int mt = 0; mt < 2; mt++)
        #pragma unroll
        for (int nt = 0; nt < 4; nt++)
            #pragma unroll
            for (int q = 0; q < 4; q++) d[mt][nt][q] = 0.f;

    for (int ch = 0; ch < 4; ch++) {
        __syncthreads();
        // Stage X chunk: 128 rows x 32 cols, float4 loads/stores
        #pragma unroll
        for (int it = 0; it < 8; it++) {
            int idx = it * 128 + tid;
            int r = idx >> 3, q = idx & 7;
            float4 v = *reinterpret_cast<const float4*>(
                x + (size_t)(row0 + r) * FF + ch * 32 + q * 4);
            *reinterpret_cast<float4*>(&Xs[r * XST + q * 4]) = v;
        }
        __syncthreads();

        // B fragments for this chunk: 4 ksteps x 4 ntiles x 2 regs
        uint32_t B0[4][4], B1[4][4];
        #pragma unroll
        for (int ks = 0; ks < 4; ks++)
            #pragma unroll
            for (int nt = 0; nt < 4; nt++) {
                B0[ks][nt] = __float_as_uint(Wsm[(ch * 32 + ks * 8 + c4) * WST + nt * 8 + g]);
                B1[ks][nt] = __float_as_uint(Wsm[(ch * 32 + ks * 8 + c4 + 4) * WST + nt * 8 + g]);
            }

        #pragma unroll
        for (int ks = 0; ks < 4; ks++) {
            uint32_t A[2][4];
            #pragma unroll
            for (int mt = 0; mt < 2; mt++) {
                const int rb = w * 32 + mt * 16;
                A[mt][0] = __float_as_uint(Xs[(rb + g) * XST + ks * 8 + c4]);
                A[mt][1] = __float_as_uint(Xs[(rb + g + 8) * XST + ks * 8 + c4]);
                A[mt][2] = __float_as_uint(Xs[(rb + g) * XST + ks * 8 + c4 + 4]);
                A[mt][3] = __float_as_uint(Xs[(rb + g + 8) * XST + ks * 8 + c4 + 4]);
            }
            #pragma unroll
            for (int mt = 0; mt < 2; mt++)
                #pragma unroll
                for (int nt = 0; nt < 4; nt++)
                    asm volatile(
                        "mma.sync.aligned.m16n8k8.row.col.f32.tf32.tf32.f32 "
                        "{%0,%1,%2,%3}, {%4,%5,%6,%7}, {%8,%9}, {%0,%1,%2,%3};"
                        : "+f"(d[mt][nt][0]), "+f"(d[mt][nt][1]),
                          "+f"(d[mt][nt][2]), "+f"(d[mt][nt][3])
                        : "r"(A[mt][0]), "r"(A[mt][1]), "r"(A[mt][2]), "r"(A[mt][3]),
                          "r"(B0[ks][nt]), "r"(B1[ks][nt]));
        }
    }

    // Epilogue: exp on FMA pipe, float2 stores (warp covers full 32B sectors)
    #pragma unroll
    for (int mt = 0; mt < 2; mt++) {
        const int row = row0 + w * 32 + mt * 16 + g;
        #pragma unroll
        for (int nt = 0; nt < 4; nt++) {
            const int col = nt * 8 + 2 * c4;
            float2 o1, o2;
            o1.x = fast_exp(d[mt][nt][0]);
            o1.y = fast_exp(d[mt][nt][1]);
            o2.x = fast_exp(d[mt][nt][2]);
            o2.y = fast_exp(d[mt][nt][3]);
            *reinterpret_cast<float2*>(&g_eem[(size_t)row * KK + col]) = o1;
            *reinterpret_cast<float2*>(&g_eem[(size_t)(row + 8) * KK + col]) = o2;
        }
    }
}

// =====================================================================
// Kernel 2: dual-stream chunked linear-space forward scan.
// One warp = two independent chunk recurrences (c0=2p, c1=2p+1) run in
// lockstep: one __syncwarp covers both streams' STS->LDS, ILP=2 hides
// the FMA/LDS chains. Uniform 96-iteration schedule; chunk 0 uses masked
// dummy warm steps. Birkhoff contraction (warmup 32) makes the starting
// direction of each chunk exact to well below fp32.
// =====================================================================
__device__ __forceinline__ float matvec32(const float* __restrict__ b,
                                          const float (&r)[32]) {
    const float4* v = reinterpret_cast<const float4*>(b);
    float4 v0 = v[0], v1 = v[1], v2 = v[2], v3 = v[3];
    float4 v4 = v[4], v5 = v[5], v6 = v[6], v7 = v[7];
    float s0 = v0.x * r[0];  s0 = fmaf(v0.y, r[1],  s0); s0 = fmaf(v0.z, r[2],  s0); s0 = fmaf(v0.w, r[3],  s0);
    float s1 = v1.x * r[4];  s1 = fmaf(v1.y, r[5],  s1); s1 = fmaf(v1.z, r[6],  s1); s1 = fmaf(v1.w, r[7],  s1);
    float s2 = v2.x * r[8];  s2 = fmaf(v2.y, r[9],  s2); s2 = fmaf(v2.z, r[10], s2); s2 = fmaf(v2.w, r[11], s2);
    float s3 = v3.x * r[12]; s3 = fmaf(v3.y, r[13], s3); s3 = fmaf(v3.z, r[14], s3); s3 = fmaf(v3.w, r[15], s3);
    float s4 = v4.x * r[16]; s4 = fmaf(v4.y, r[17], s4); s4 = fmaf(v4.z, r[18], s4); s4 = fmaf(v4.w, r[19], s4);
    float s5 = v5.x * r[20]; s5 = fmaf(v5.y, r[21], s5); s5 = fmaf(v5.z, r[22], s5); s5 = fmaf(v5.w, r[23], s5);
    float s6 = v6.x * r[24]; s6 = fmaf(v6.y, r[25], s6); s6 = fmaf(v6.z, r[26], s6); s6 = fmaf(v6.w, r[27], s6);
    float s7 = v7.x * r[28]; s7 = fmaf(v7.y, r[29], s7); s7 = fmaf(v7.z, r[30], s7); s7 = fmaf(v7.w, r[31], s7);
    return ((s0 + s1) + (s2 + s3)) + ((s4 + s5) + (s6 + s7));
}

__device__ __forceinline__ void dual_step(float& a0, float& a1,
                                          const float (&r)[32], float* sbuf,
                                          float e0, int m0, float e1, int m1,
                                          int k, int ph) {
    float* b0 = sbuf + (ph << 6);
    float* b1 = b0 + 32;
    b0[k] = a0;
    b1[k] = a1;
    __syncwarp();
    float S0 = matvec32(b0, r);
    float S1 = matvec32(b1, r);
    a0 = m0 ? S0 * e0 : a0;
    a1 = m1 ? S1 * e1 : a1;
}

__device__ __forceinline__ void renorm(float& a, int& oexp) {
    float mx = a;
    #pragma unroll
    for (int off = 16; off > 0; off >>= 1)
        mx = fmaxf(mx, __shfl_xor_sync(0xffffffffu, mx, off));
    int ei = (__float_as_int(mx) >> 23) & 255;
    oexp += ei - 127;
    a *= __int_as_float((254 - ei) << 23);     // exact 2^(127-ei)
}

__device__ __forceinline__ float bsum(float a) {
    float s = a;
    #pragma unroll
    for (int off = 16; off > 0; off >>= 1)
        s += __shfl_xor_sync(0xffffffffu, s, off);
    return s;
}

__global__ __launch_bounds__(32) void scan2_kernel(const int* __restrict__ mask,
                                                   const float* __restrict__ trans) {
    __shared__ __align__(16) float sbuf[128];   // [phase][stream][32]
    const int b  = blockIdx.x >> 3;             // batch
    const int p  = blockIdx.x & 7;              // pair
    const int c0 = 2 * p, c1 = 2 * p + 1;
    const int k  = threadIdx.x;

    float r[32];                                // expT column k
    #pragma unroll
    for (int j = 0; j < 32; j++)
        r[j] = expf(trans[j * KK + k]);

    const float* eb = g_eem + (size_t)b * TT * KK;
    const int*   mb = mask + (size_t)b * TT;

    float a0 = (c0 == 0) ? eb[k] : 1.f;
    float a1 = 1.f;
    int ox0 = 0, ox1 = 0;
    float s0snap = 0.f, s1snap = 0.f;
    int ox0s = 0, ox1s = 0;

    const int base1 = c1 * CLEN - WARM;

    #pragma unroll 1
    for (int blk = 0; blk < 12; blk++) {
        float e0[8], e1[8];
        int m0[8], m1[8];
        #pragma unroll
        for (int i = 0; i < 8; i++) {
            const int i96 = blk * 8 + i;
            int t0, v0;
            if (c0 == 0) {
                t0 = 1 + i96 - WARM;                 // measured span [1, 64)
                v0 = (t0 >= 1) && (t0 < CLEN);
                if (t0 < 1) t0 = 1;
            } else {
                t0 = c0 * CLEN - WARM + i96;
                v0 = 1;
            }
            const int t1 = base1 + i96;
            e0[i] = eb[t0 * KK + k];
            m0[i] = v0 ? mb[t0] : 0;
            e1[i] = eb[t1 * KK + k];
            m1[i] = mb[t1];
        }
        #pragma unroll
        for (int i = 0; i < 8; i++)
            dual_step(a0, a1, r, sbuf, e0[i], m0[i], e1[i], m1[i], k, i & 1);
        renorm(a0, ox0);
        renorm(a1, ox1);
        if (blk == 3) {                          // state after warmup (i96 == 32)
            s0snap = (c0 == 0) ? 0.f : logf(bsum(a0));
            ox0s   = (c0 == 0) ? ox0 - ox0 : ox0;  // 0 for chunk 0 (count all renorms)
            if (c0 == 0) ox0s = 0;
            s1snap = logf(bsum(a1));
            ox1s   = ox1;
        }
    }

    const float LN2 = 0.69314718055994531f;
    float D0 = (float)(ox0 - ox0s) * LN2 + logf(bsum(a0)) - s0snap;
    float D1 = (float)(ox1 - ox1s) * LN2 + logf(bsum(a1)) - s1snap;
    if (k == 0) {
        g_part[b * NCH + c0] = D0;
        g_part[b * NCH + c1] = D1;
    }
}

// =====================================================================
// Kernel 3: deterministic reduction of 2048 chunk contributions
// =====================================================================
__global__ __launch_bounds__(256) void reduce_kernel(float* __restrict__ out) {
    __shared__ double ws[8];
    const int t = threadIdx.x;
    double v = 0.0;
    #pragma unroll
    for (int i = 0; i < 8; i++) v += (double)g_part[t * 8 + i];
    #pragma unroll
    for (int off = 16; off > 0; off >>= 1)
        v += __shfl_xor_sync(0xffffffffu, v, off);
    if ((t & 31) == 0) ws[t >> 5] = v;
    __syncthreads();
    if (t == 0) {
        double s = 0.0;
        #pragma unroll
        for (int i = 0; i < 8; i++) s += ws[i];
        out[0] = (float)s;
    }
}

extern "C" void kernel_launch(void* const* d_in, const int* in_sizes, int n_in,
                              void* d_out, int out_size) {
    const float* x     = (const float*)d_in[0];
    const int*   mask  = (const int*)d_in[1];
    const float* W     = (const float*)d_in[2];
    const float* trans = (const float*)d_in[3];

    emis_mma<<<(BATCH * TT) / 128, 128>>>(x, W);
    scan2_kernel<<<BATCH * NCH / 2, 32>>>(mask, trans);
    reduce_kernel<<<1, 256>>>((float*)d_out);
}

// round 7
// speedup vs baseline: 6.0831x; 1.0934x over previous
#include <cuda_runtime.h>
#include <cstdint>
#include <math.h>

#define BATCH 128
#define TT    1024
#define FF    128
#define KK    32
#define NCH   16      // chunks per batch
#define CLEN  64      // steps per chunk
#define WARM  32      // warmup steps

// Scratch (device globals: allocation-free per harness rules)
static __device__ float g_eem[(size_t)BATCH * TT * KK];   // exp(em), 16MB
static __device__ float g_part[BATCH * NCH];              // per-(batch,chunk) D

// fast exp on the FMA pipe (rel err ~4e-5 over |x|<~3); avoids the MUFU floor
__device__ __forceinline__ float fast_exp(float x) {
    float t = x * 1.4426950408889634f;
    float n = rintf(t);
    float f = t - n;
    float p = 0.0096853f;
    p = fmaf(p, f, 0.05550411f);
    p = fmaf(p, f, 0.24022651f);
    p = fmaf(p, f, 0.69314718f);
    p = fmaf(p, f, 1.0f);
    return __int_as_float(__float_as_int(p) + (((int)n) << 23));
}

// =====================================================================
// Kernel 1: emission GEMM on mma.sync tf32 + fast exp, double-buffered.
//   eem[row][k] = exp(sum_f x[row][f] * W[f][k])
// CTA: 128 threads (4 warps), tile 128 rows x 32 states, K=128 in 4
// chunks. LDG of chunk i+1 overlaps mma on chunk i (regs->STS after).
// =====================================================================
#define XST 36   // Xs row stride (words): conflict-free A-fragment LDS
#define WST 40   // Wsm row stride (words): conflict-free B-fragment LDS

__global__ __launch_bounds__(128) void emis_mma(const float* __restrict__ x,
                                                const float* __restrict__ W) {
    __shared__ __align__(16) float Xs[2][128 * XST];   // 36.9KB double buffer
    __shared__ __align__(16) float Wsm[128 * WST];     // 20.5KB

    const int tid  = threadIdx.x;
    const int lane = tid & 31;
    const int w    = tid >> 5;
    const int g    = lane >> 2;      // 0..7
    const int c4   = lane & 3;       // 0..3
    const int row0 = blockIdx.x * 128;

    const int sr = tid >> 3;         // staging row (0..15 step), q below
    const int sq = tid & 7;          // staging float4 index

    // Stage all of W: [f][n] at stride WST
    #pragma unroll
    for (int i = 0; i < 32; i++) {
        int idx = i * 128 + tid;
        Wsm[(idx >> 5) * WST + (idx & 31)] = W[idx];
    }

    // Prologue: load + store chunk 0
    {
        float4 v[8];
        #pragma unroll
        for (int it = 0; it < 8; it++)
            v[it] = *reinterpret_cast<const float4*>(
                x + (size_t)(row0 + it * 16 + sr) * FF + sq * 4);
        #pragma unroll
        for (int it = 0; it < 8; it++)
            *reinterpret_cast<float4*>(&Xs[0][(it * 16 + sr) * XST + sq * 4]) = v[it];
    }
    __syncthreads();

    float d[2][4][4];
    #pragma unroll
    for (int mt = 0; mt < 2; mt++)
        #pragma unroll
        for (int nt = 0; nt < 4; nt++)
            #pragma unroll
            for (int q = 0; q < 4; q++) d[mt][nt][q] = 0.f;

    #pragma unroll
    for (int ch = 0; ch < 4; ch++) {
        const int cur = ch & 1;
        // Issue next chunk's LDGs first (latency overlapped with mma below)
        float4 v[8];
        if (ch < 3) {
            #pragma unroll
            for (int it = 0; it < 8; it++)
                v[it] = *reinterpret_cast<const float4*>(
                    x + (size_t)(row0 + it * 16 + sr) * FF + (ch + 1) * 32 + sq * 4);
        }

        // B fragments for this chunk
        uint32_t B0[4][4], B1[4][4];
        #pragma unroll
        for (int ks = 0; ks < 4; ks++)
            #pragma unroll
            for (int nt = 0; nt < 4; nt++) {
                B0[ks][nt] = __float_as_uint(Wsm[(ch * 32 + ks * 8 + c4) * WST + nt * 8 + g]);
                B1[ks][nt] = __float_as_uint(Wsm[(ch * 32 + ks * 8 + c4 + 4) * WST + nt * 8 + g]);
            }

        #pragma unroll
        for (int ks = 0; ks < 4; ks++) {
            uint32_t A[2][4];
            #pragma unroll
            for (int mt = 0; mt < 2; mt++) {
                const int rb = w * 32 + mt * 16;
                A[mt][0] = __float_as_uint(Xs[cur][(rb + g) * XST + ks * 8 + c4]);
                A[mt][1] = __float_as_uint(Xs[cur][(rb + g + 8) * XST + ks * 8 + c4]);
                A[mt][2] = __float_as_uint(Xs[cur][(rb + g) * XST + ks * 8 + c4 + 4]);
                A[mt][3] = __float_as_uint(Xs[cur][(rb + g + 8) * XST + ks * 8 + c4 + 4]);
            }
            #pragma unroll
            for (int mt = 0; mt < 2; mt++)
                #pragma unroll
                for (int nt = 0; nt < 4; nt++)
                    asm volatile(
                        "mma.sync.aligned.m16n8k8.row.col.f32.tf32.tf32.f32 "
                        "{%0,%1,%2,%3}, {%4,%5,%6,%7}, {%8,%9}, {%0,%1,%2,%3};"
                        : "+f"(d[mt][nt][0]), "+f"(d[mt][nt][1]),
                          "+f"(d[mt][nt][2]), "+f"(d[mt][nt][3])
                        : "r"(A[mt][0]), "r"(A[mt][1]), "r"(A[mt][2]), "r"(A[mt][3]),
                          "r"(B0[ks][nt]), "r"(B1[ks][nt]));
        }

        if (ch < 3) {
            #pragma unroll
            for (int it = 0; it < 8; it++)
                *reinterpret_cast<float4*>(&Xs[cur ^ 1][(it * 16 + sr) * XST + sq * 4]) = v[it];
            __syncthreads();
        }
    }

    // Epilogue: exp on FMA pipe, float2 stores
    #pragma unroll
    for (int mt = 0; mt < 2; mt++) {
        const int row = row0 + w * 32 + mt * 16 + g;
        #pragma unroll
        for (int nt = 0; nt < 4; nt++) {
            const int col = nt * 8 + 2 * c4;
            float2 o1, o2;
            o1.x = fast_exp(d[mt][nt][0]);
            o1.y = fast_exp(d[mt][nt][1]);
            o2.x = fast_exp(d[mt][nt][2]);
            o2.y = fast_exp(d[mt][nt][3]);
            *reinterpret_cast<float2*>(&g_eem[(size_t)row * KK + col]) = o1;
            *reinterpret_cast<float2*>(&g_eem[(size_t)(row + 8) * KK + col]) = o2;
        }
    }
}

// =====================================================================
// Kernel 2: chunked linear-space forward scan, 8 warps/CTA.
// Warp = one (batch, chunk); lane = state k. smem-broadcast matvec
// (1 STS + 8 LDS.128 per step). Birkhoff-contraction warmup (32 steps)
// makes each chunk's starting direction exact to below fp32.
// =====================================================================
__device__ __forceinline__ float matvec32(const float* __restrict__ b,
                                          const float (&r)[32]) {
    const float4* v = reinterpret_cast<const float4*>(b);
    float4 v0 = v[0], v1 = v[1], v2 = v[2], v3 = v[3];
    float4 v4 = v[4], v5 = v[5], v6 = v[6], v7 = v[7];
    float s0 = v0.x * r[0];  s0 = fmaf(v0.y, r[1],  s0); s0 = fmaf(v0.z, r[2],  s0); s0 = fmaf(v0.w, r[3],  s0);
    float s1 = v1.x * r[4];  s1 = fmaf(v1.y, r[5],  s1); s1 = fmaf(v1.z, r[6],  s1); s1 = fmaf(v1.w, r[7],  s1);
    float s2 = v2.x * r[8];  s2 = fmaf(v2.y, r[9],  s2); s2 = fmaf(v2.z, r[10], s2); s2 = fmaf(v2.w, r[11], s2);
    float s3 = v3.x * r[12]; s3 = fmaf(v3.y, r[13], s3); s3 = fmaf(v3.z, r[14], s3); s3 = fmaf(v3.w, r[15], s3);
    float s4 = v4.x * r[16]; s4 = fmaf(v4.y, r[17], s4); s4 = fmaf(v4.z, r[18], s4); s4 = fmaf(v4.w, r[19], s4);
    float s5 = v5.x * r[20]; s5 = fmaf(v5.y, r[21], s5); s5 = fmaf(v5.z, r[22], s5); s5 = fmaf(v5.w, r[23], s5);
    float s6 = v6.x * r[24]; s6 = fmaf(v6.y, r[25], s6); s6 = fmaf(v6.z, r[26], s6); s6 = fmaf(v6.w, r[27], s6);
    float s7 = v7.x * r[28]; s7 = fmaf(v7.y, r[29], s7); s7 = fmaf(v7.z, r[30], s7); s7 = fmaf(v7.w, r[31], s7);
    return ((s0 + s1) + (s2 + s3)) + ((s4 + s5) + (s6 + s7));
}

__device__ __forceinline__ void crf_step(float& a, const float (&r)[32],
                                         float* sbuf, float e, int m,
                                         int k, int ph) {
    float* b = sbuf + (ph << 5);
    b[k] = a;
    __syncwarp();
    float s = matvec32(b, r);
    a = m ? s * e : a;
}

__device__ __forceinline__ void renorm(float& a, int& oexp) {
    float mx = a;
    #pragma unroll
    for (int off = 16; off > 0; off >>= 1)
        mx = fmaxf(mx, __shfl_xor_sync(0xffffffffu, mx, off));
    int ei = (__float_as_int(mx) >> 23) & 255;
    oexp += ei - 127;
    a *= __int_as_float((254 - ei) << 23);     // exact 2^(127-ei)
}

__device__ __forceinline__ float bsum(float a) {
    float s = a;
    #pragma unroll
    for (int off = 16; off > 0; off >>= 1)
        s += __shfl_xor_sync(0xffffffffu, s, off);
    return s;
}

__device__ __forceinline__ void run_span(float& a, const float (&r)[32],
                                         float* sbuf,
                                         const float* __restrict__ eemb,
                                         const int* __restrict__ mb,
                                         int t, int tend, int k, int& oexp) {
    float eA[8]; int mA[8];
    if (t + 8 <= tend) {
        #pragma unroll
        for (int i = 0; i < 8; i++) { eA[i] = eemb[(t + i) * KK + k]; mA[i] = mb[t + i]; }
    }
    while (t + 8 <= tend) {
        float eB[8]; int mB[8];
        if (t + 16 <= tend) {
            #pragma unroll
            for (int i = 0; i < 8; i++) { eB[i] = eemb[(t + 8 + i) * KK + k]; mB[i] = mb[t + 8 + i]; }
        } else {
            #pragma unroll
            for (int i = 0; i < 8; i++) { eB[i] = 0.f; mB[i] = 0; }
        }
        #pragma unroll
        for (int i = 0; i < 8; i++) crf_step(a, r, sbuf, eA[i], mA[i], k, i & 1);
        renorm(a, oexp);
        #pragma unroll
        for (int i = 0; i < 8; i++) { eA[i] = eB[i]; mA[i] = mB[i]; }
        t += 8;
    }
    for (; t < tend; t++)
        crf_step(a, r, sbuf, eemb[t * KK + k], mb[t], k, t & 1);
}

__global__ __launch_bounds__(256) void scan8_kernel(const int* __restrict__ mask,
                                                    const float* __restrict__ trans) {
    __shared__ __align__(16) float sbuf[8][64];    // per-warp double buffer
    const int b    = blockIdx.x >> 1;
    const int half = blockIdx.x & 1;
    const int wi   = threadIdx.x >> 5;
    const int k    = threadIdx.x & 31;
    const int c    = half * 8 + wi;

    float r[32];                                   // expT column k
    #pragma unroll
    for (int j = 0; j < 32; j++)
        r[j] = expf(trans[j * KK + k]);

    const float* eb = g_eem + (size_t)b * TT * KK;
    const int*   mb = mask + (size_t)b * TT;
    float* sb = sbuf[wi];

    float a, m0 = 0.f;
    int oexp = 0, dummy = 0;

    if (c == 0) {
        a = eb[k];                                 // alpha0 = em0 (exp form)
        run_span(a, r, sb, eb, mb, 1, CLEN, k, oexp);
    } else {
        a = 1.f;                                   // uniform init, forgotten by warmup
        const int ts = c * CLEN;
        run_span(a, r, sb, eb, mb, ts - WARM, ts, k, dummy);
        m0 = logf(bsum(a));
        run_span(a, r, sb, eb, mb, ts, ts + CLEN, k, oexp);
    }

    float D = (float)oexp * 0.69314718055994531f + logf(bsum(a)) - m0;
    if (k == 0) g_part[b * NCH + c] = D;
}

// =====================================================================
// Kernel 3: deterministic reduction of 2048 chunk contributions
// =====================================================================
__global__ __launch_bounds__(256) void reduce_kernel(float* __restrict__ out) {
    __shared__ double ws[8];
    const int t = threadIdx.x;
    double v = 0.0;
    #pragma unroll
    for (int i = 0; i < 8; i++) v += (double)g_part[t * 8 + i];
    #pragma unroll
    for (int off = 16; off > 0; off >>= 1)
        v += __shfl_xor_sync(0xffffffffu, v, off);
    if ((t & 31) == 0) ws[t >> 5] = v;
    __syncthreads();
    if (t == 0) {
        double s = 0.0;
        #pragma unroll
        for (int i = 0; i < 8; i++) s += ws[i];
        out[0] = (float)s;
    }
}

extern "C" void kernel_launch(void* const* d_in, const int* in_sizes, int n_in,
                              void* d_out, int out_size) {
    const float* x     = (const float*)d_in[0];
    const int*   mask  = (const int*)d_in[1];
    const float* W     = (const float*)d_in[2];
    const float* trans = (const float*)d_in[3];

    emis_mma<<<(BATCH * TT) / 128, 128>>>(x, W);
    scan8_kernel<<<BATCH * 2, 256>>>(mask, trans);
    reduce_kernel<<<1, 256>>>((float*)d_out);
}

// round 8
// speedup vs baseline: 6.3786x; 1.0486x over previous
#include <cuda_runtime.h>
#include <cstdint>
#include <math.h>

#define BATCH 128
#define TT    1024
#define FF    128
#define KK    32
#define NCH   32      // chunks per batch
#define CLEN  32      // measured steps per chunk
#define WARM  32      // warmup steps
#define ITERS 64      // WARM + CLEN

// Scratch (device globals: allocation-free per harness rules)
static __device__ float g_eem[(size_t)BATCH * TT * KK];   // exp(em), 16MB
static __device__ float g_part[BATCH * NCH];              // per-(batch,chunk) D

// fast exp on the FMA pipe (rel err ~4e-5 over |x|<~3); avoids the MUFU floor
__device__ __forceinline__ float fast_exp(float x) {
    float t = x * 1.4426950408889634f;
    float n = rintf(t);
    float f = t - n;
    float p = 0.0096853f;
    p = fmaf(p, f, 0.05550411f);
    p = fmaf(p, f, 0.24022651f);
    p = fmaf(p, f, 0.69314718f);
    p = fmaf(p, f, 1.0f);
    return __int_as_float(__float_as_int(p) + (((int)n) << 23));
}

__device__ __forceinline__ uint32_t smem_u32(const void* p) {
    uint32_t a;
    asm("{ .reg .u64 t; cvta.to.shared.u64 t, %1; cvt.u32.u64 %0, t; }" : "=r"(a) : "l"(p));
    return a;
}
__device__ __forceinline__ void cpasync16(uint32_t dst, const void* src) {
    asm volatile("cp.async.cg.shared.global [%0], [%1], 16;" :: "r"(dst), "l"(src));
}
#define CP_COMMIT() asm volatile("cp.async.commit_group;" ::: "memory")
#define CP_WAIT(n)  asm volatile("cp.async.wait_group %0;" :: "n"(n) : "memory")

// =====================================================================
// Kernel 1: emission GEMM on mma.sync tf32 + fast exp, double-buffered.
// (unchanged from R7: 20.3us)
// =====================================================================
#define XST 36
#define WST 40

__global__ __launch_bounds__(128) void emis_mma(const float* __restrict__ x,
                                                const float* __restrict__ W) {
    __shared__ __align__(16) float Xs[2][128 * XST];
    __shared__ __align__(16) float Wsm[128 * WST];

    const int tid  = threadIdx.x;
    const int lane = tid & 31;
    const int w    = tid >> 5;
    const int g    = lane >> 2;
    const int c4   = lane & 3;
    const int row0 = blockIdx.x * 128;

    const int sr = tid >> 3;
    const int sq = tid & 7;

    #pragma unroll
    for (int i = 0; i < 32; i++) {
        int idx = i * 128 + tid;
        Wsm[(idx >> 5) * WST + (idx & 31)] = W[idx];
    }

    {
        float4 v[8];
        #pragma unroll
        for (int it = 0; it < 8; it++)
            v[it] = *reinterpret_cast<const float4*>(
                x + (size_t)(row0 + it * 16 + sr) * FF + sq * 4);
        #pragma unroll
        for (int it = 0; it < 8; it++)
            *reinterpret_cast<float4*>(&Xs[0][(it * 16 + sr) * XST + sq * 4]) = v[it];
    }
    __syncthreads();

    float d[2][4][4];
    #pragma unroll
    for (int mt = 0; mt < 2; mt++)
        #pragma unroll
        for (int nt = 0; nt < 4; nt++)
            #pragma unroll
            for (int q = 0; q < 4; q++) d[mt][nt][q] = 0.f;

    #pragma unroll
    for (int ch = 0; ch < 4; ch++) {
        const int cur = ch & 1;
        float4 v[8];
        if (ch < 3) {
            #pragma unroll
            for (int it = 0; it < 8; it++)
                v[it] = *reinterpret_cast<const float4*>(
                    x + (size_t)(row0 + it * 16 + sr) * FF + (ch + 1) * 32 + sq * 4);
        }

        uint32_t B0[4][4], B1[4][4];
        #pragma unroll
        for (int ks = 0; ks < 4; ks++)
            #pragma unroll
            for (int nt = 0; nt < 4; nt++) {
                B0[ks][nt] = __float_as_uint(Wsm[(ch * 32 + ks * 8 + c4) * WST + nt * 8 + g]);
                B1[ks][nt] = __float_as_uint(Wsm[(ch * 32 + ks * 8 + c4 + 4) * WST + nt * 8 + g]);
            }

        #pragma unroll
        for (int ks = 0; ks < 4; ks++) {
            uint32_t A[2][4];
            #pragma unroll
            for (int mt = 0; mt < 2; mt++) {
                const int rb = w * 32 + mt * 16;
                A[mt][0] = __float_as_uint(Xs[cur][(rb + g) * XST + ks * 8 + c4]);
                A[mt][1] = __float_as_uint(Xs[cur][(rb + g + 8) * XST + ks * 8 + c4]);
                A[mt][2] = __float_as_uint(Xs[cur][(rb + g) * XST + ks * 8 + c4 + 4]);
                A[mt][3] = __float_as_uint(Xs[cur][(rb + g + 8) * XST + ks * 8 + c4 + 4]);
            }
            #pragma unroll
            for (int mt = 0; mt < 2; mt++)
                #pragma unroll
                for (int nt = 0; nt < 4; nt++)
                    asm volatile(
                        "mma.sync.aligned.m16n8k8.row.col.f32.tf32.tf32.f32 "
                        "{%0,%1,%2,%3}, {%4,%5,%6,%7}, {%8,%9}, {%0,%1,%2,%3};"
                        : "+f"(d[mt][nt][0]), "+f"(d[mt][nt][1]),
                          "+f"(d[mt][nt][2]), "+f"(d[mt][nt][3])
                        : "r"(A[mt][0]), "r"(A[mt][1]), "r"(A[mt][2]), "r"(A[mt][3]),
                          "r"(B0[ks][nt]), "r"(B1[ks][nt]));
        }

        if (ch < 3) {
            #pragma unroll
            for (int it = 0; it < 8; it++)
                *reinterpret_cast<float4*>(&Xs[cur ^ 1][(it * 16 + sr) * XST + sq * 4]) = v[it];
            __syncthreads();
        }
    }

    #pragma unroll
    for (int mt = 0; mt < 2; mt++) {
        const int row = row0 + w * 32 + mt * 16 + g;
        #pragma unroll
        for (int nt = 0; nt < 4; nt++) {
            const int col = nt * 8 + 2 * c4;
            float2 o1, o2;
            o1.x = fast_exp(d[mt][nt][0]);
            o1.y = fast_exp(d[mt][nt][1]);
            o2.x = fast_exp(d[mt][nt][2]);
            o2.y = fast_exp(d[mt][nt][3]);
            *reinterpret_cast<float2*>(&g_eem[(size_t)row * KK + col]) = o1;
            *reinterpret_cast<float2*>(&g_eem[(size_t)(row + 8) * KK + col]) = o2;
        }
    }
}

// =====================================================================
// Kernel 2: tensor-core scan. One warp = 16 chunk-streams of one batch.
// Per step: alpha(16x32) @ expT(32x32) via 16x mma.sync.m16n8k8.tf32,
// elementwise eem multiply + mask, renorm every 8 steps.
// alpha D-layout regs <-> A-fragments via double-buffered smem tile.
// eem prefetched with cp.async in 4-step double-buffered blocks.
// Chunk c covers t in [32c, 32c+31] (c>=1); chunk 0 covers [1,31].
// 32-step Birkhoff-contraction warmup forms each chunk's direction.
// =====================================================================
#define AST 36   // alpha tile stride: LDS bank (4g+c4) conflict-free

__global__ __launch_bounds__(32) void scan_mma(const int* __restrict__ mask,
                                               const float* __restrict__ trans) {
    __shared__ __align__(16) float E4[2][4][16][AST];  // eem stage, 2 blocks x 4 steps
    __shared__ __align__(16) float al[2][16][AST];     // alpha tile double buffer

    const int b    = blockIdx.x >> 1;
    const int cb   = (blockIdx.x & 1) * 16;            // chunk base of this warp
    const int lane = threadIdx.x;
    const int g    = lane >> 2;                        // 0..7
    const int c4   = lane & 3;                         // 0..3

    // B fragments of E = exp(transition): col-major 32x32, 4 ktiles x 4 ntiles
    uint32_t B0[4][4], B1[4][4];
    #pragma unroll
    for (int kt = 0; kt < 4; kt++)
        #pragma unroll
        for (int nt = 0; nt < 4; nt++) {
            B0[kt][nt] = __float_as_uint(expf(trans[(kt * 8 + c4) * KK + nt * 8 + g]));
            B1[kt][nt] = __float_as_uint(expf(trans[(kt * 8 + c4 + 4) * KK + nt * 8 + g]));
        }

    const float* eb = g_eem + (size_t)b * TT * KK;
    const int*   mb = mask + (size_t)b * TT;

    const int ch_g = cb + g;           // chunk of row g
    const int ch_h = cb + g + 8;       // chunk of row g+8 (never 0)
    const bool g0  = (ch_g == 0);
    const int base_g = 32 * ch_g - 32;
    const int base_h = 32 * ch_h - 32;

    // alpha state in D layout: d[nt][0,1] = row g cols nt*8+2c4(+1); [2,3] = row g+8
    float d[4][4];
    #pragma unroll
    for (int nt = 0; nt < 4; nt++) {
        d[nt][0] = g0 ? eb[nt * 8 + 2 * c4]     : 1.f;
        d[nt][1] = g0 ? eb[nt * 8 + 2 * c4 + 1] : 1.f;
        d[nt][2] = 1.f;
        d[nt][3] = 1.f;
    }
    // write initial alpha to buffer 0 (iter 0 reads rb=0)
    #pragma unroll
    for (int nt = 0; nt < 4; nt++) {
        *reinterpret_cast<float2*>(&al[0][g][nt * 8 + 2 * c4]) = make_float2(d[nt][0], d[nt][1]);
        *reinterpret_cast<float2*>(&al[0][g + 8][nt * 8 + 2 * c4]) = make_float2(d[nt][2], d[nt][3]);
    }
    __syncwarp();

    // eem staging: 16 cp.async per lane per 4-step block
    const int sl = lane & 7;           // float4 index within row
    const int sg = lane >> 3;          // 0..3: combo subindex
    auto stage_block = [&](int blk) {
        #pragma unroll
        for (int it = 0; it < 16; it++) {
            int combo = it * 4 + sg;   // 0..63
            int ii = combo & 3, r = combo >> 2;
            int ch = cb + r;
            int i  = blk * 4 + ii;
            int t  = (ch == 0) ? max(i - 32, 0) : (32 * ch - 32 + i);
            cpasync16(smem_u32(&E4[blk & 1][ii][r][sl * 4]), eb + (size_t)t * KK + sl * 4);
        }
        CP_COMMIT();
    };

    stage_block(0);

    int oe_g = 0, oe_h = 0, oes_g = 0, oes_h = 0;
    float snl_g = 0.f, snl_h = 0.f;
    const float z = 0.f;

    #pragma unroll 1
    for (int blk = 0; blk < 16; blk++) {
        if (blk < 15) stage_block(blk + 1);
        if (blk < 15) { CP_WAIT(1); } else { CP_WAIT(0); }
        __syncwarp();
        const int buf = blk & 1;

        // masks for this block (broadcast loads within quads; all-ones dataset -> L1 hot)
        int mg[4], mh[4];
        #pragma unroll
        for (int ii = 0; ii < 4; ii++) {
            int i = blk * 4 + ii;
            int tg = g0 ? max(i - 32, 0) : base_g + i;
            mg[ii] = (g0 && i < 33) ? 0 : mb[tg];
            mh[ii] = mb[base_h + i];
        }

        #pragma unroll
        for (int ii = 0; ii < 4; ii++) {
            const int i  = blk * 4 + ii;
            const int rb = i & 1, wb = rb ^ 1;

            // A fragments from alpha tile
            uint32_t A0[4], A1[4], A2[4], A3[4];
            #pragma unroll
            for (int kt = 0; kt < 4; kt++) {
                A0[kt] = __float_as_uint(al[rb][g][kt * 8 + c4]);
                A1[kt] = __float_as_uint(al[rb][g + 8][kt * 8 + c4]);
                A2[kt] = __float_as_uint(al[rb][g][kt * 8 + c4 + 4]);
                A3[kt] = __float_as_uint(al[rb][g + 8][kt * 8 + c4 + 4]);
            }

            // 16 MMAs: two 2-deep accumulation chains per ntile
            float dA[4][4], dB[4][4];
            #pragma unroll
            for (int nt = 0; nt < 4; nt++) {
                asm volatile(
                    "mma.sync.aligned.m16n8k8.row.col.f32.tf32.tf32.f32 "
                    "{%0,%1,%2,%3}, {%4,%5,%6,%7}, {%8,%9}, {%10,%11,%12,%13};"
                    : "=f"(dA[nt][0]), "=f"(dA[nt][1]), "=f"(dA[nt][2]), "=f"(dA[nt][3])
                    : "r"(A0[0]), "r"(A1[0]), "r"(A2[0]), "r"(A3[0]),
                      "r"(B0[0][nt]), "r"(B1[0][nt]), "f"(z), "f"(z), "f"(z), "f"(z));
                asm volatile(
                    "mma.sync.aligned.m16n8k8.row.col.f32.tf32.tf32.f32 "
                    "{%0,%1,%2,%3}, {%4,%5,%6,%7}, {%8,%9}, {%0,%1,%2,%3};"
                    : "+f"(dA[nt][0]), "+f"(dA[nt][1]), "+f"(dA[nt][2]), "+f"(dA[nt][3])
                    : "r"(A0[1]), "r"(A1[1]), "r"(A2[1]), "r"(A3[1]),
                      "r"(B0[1][nt]), "r"(B1[1][nt]));
                asm volatile(
                    "mma.sync.aligned.m16n8k8.row.col.f32.tf32.tf32.f32 "
                    "{%0,%1,%2,%3}, {%4,%5,%6,%7}, {%8,%9}, {%10,%11,%12,%13};"
                    : "=f"(dB[nt][0]), "=f"(dB[nt][1]), "=f"(dB[nt][2]), "=f"(dB[nt][3])
                    : "r"(A0[2]), "r"(A1[2]), "r"(A2[2]), "r"(A3[2]),
                      "r"(B0[2][nt]), "r"(B1[2][nt]), "f"(z), "f"(z), "f"(z), "f"(z));
                asm volatile(
                    "mma.sync.aligned.m16n8k8.row.col.f32.tf32.tf32.f32 "
                    "{%0,%1,%2,%3}, {%4,%5,%6,%7}, {%8,%9}, {%0,%1,%2,%3};"
                    : "+f"(dB[nt][0]), "+f"(dB[nt][1]), "+f"(dB[nt][2]), "+f"(dB[nt][3])
                    : "r"(A0[3]), "r"(A1[3]), "r"(A2[3]), "r"(A3[3]),
                      "r"(B0[3][nt]), "r"(B1[3][nt]));
            }

            // eem multiply + mask select
            #pragma unroll
            for (int nt = 0; nt < 4; nt++) {
                float2 eg = *reinterpret_cast<const float2*>(&E4[buf][ii][g][nt * 8 + 2 * c4]);
                float2 eh = *reinterpret_cast<const float2*>(&E4[buf][ii][g + 8][nt * 8 + 2 * c4]);
                float n0 = (dA[nt][0] + dB[nt][0]) * eg.x;
                float n1 = (dA[nt][1] + dB[nt][1]) * eg.y;
                float n2 = (dA[nt][2] + dB[nt][2]) * eh.x;
                float n3 = (dA[nt][3] + dB[nt][3]) * eh.y;
                d[nt][0] = mg[ii] ? n0 : d[nt][0];
                d[nt][1] = mg[ii] ? n1 : d[nt][1];
                d[nt][2] = mh[ii] ? n2 : d[nt][2];
                d[nt][3] = mh[ii] ? n3 : d[nt][3];
            }

            // renorm every 8 steps (exact power-of-2 per row)
            if ((i & 7) == 7) {
                float mxg = d[0][0], mxh = d[0][2];
                #pragma unroll
                for (int nt = 0; nt < 4; nt++) {
                    mxg = fmaxf(mxg, fmaxf(d[nt][0], d[nt][1]));
                    mxh = fmaxf(mxh, fmaxf(d[nt][2], d[nt][3]));
                }
                mxg = fmaxf(mxg, __shfl_xor_sync(0xffffffffu, mxg, 1));
                mxg = fmaxf(mxg, __shfl_xor_sync(0xffffffffu, mxg, 2));
                mxh = fmaxf(mxh, __shfl_xor_sync(0xffffffffu, mxh, 1));
                mxh = fmaxf(mxh, __shfl_xor_sync(0xffffffffu, mxh, 2));
                int eig = (__float_as_int(mxg) >> 23) & 255;
                int eih = (__float_as_int(mxh) >> 23) & 255;
                oe_g += eig - 127;
                oe_h += eih - 127;
                float sg_ = __int_as_float((254 - eig) << 23);
                float sh_ = __int_as_float((254 - eih) << 23);
                #pragma unroll
                for (int nt = 0; nt < 4; nt++) {
                    d[nt][0] *= sg_; d[nt][1] *= sg_;
                    d[nt][2] *= sh_; d[nt][3] *= sh_;
                }
            }

            // snapshot after warmup (end of iter 31)
            if (i == 31) {
                float sg_ = 0.f, sh_ = 0.f;
                #pragma unroll
                for (int nt = 0; nt < 4; nt++) {
                    sg_ += d[nt][0] + d[nt][1];
                    sh_ += d[nt][2] + d[nt][3];
                }
                sg_ += __shfl_xor_sync(0xffffffffu, sg_, 1);
                sg_ += __shfl_xor_sync(0xffffffffu, sg_, 2);
                sh_ += __shfl_xor_sync(0xffffffffu, sh_, 1);
                sh_ += __shfl_xor_sync(0xffffffffu, sh_, 2);
                snl_g = g0 ? 0.f : logf(sg_);
                oes_g = g0 ? 0 : oe_g;
                snl_h = logf(sh_);
                oes_h = oe_h;
            }

            // write alpha to the other buffer
            #pragma unroll
            for (int nt = 0; nt < 4; nt++) {
                *reinterpret_cast<float2*>(&al[wb][g][nt * 8 + 2 * c4]) =
                    make_float2(d[nt][0], d[nt][1]);
                *reinterpret_cast<float2*>(&al[wb][g + 8][nt * 8 + 2 * c4]) =
                    make_float2(d[nt][2], d[nt][3]);
            }
            __syncwarp();
        }
    }

    // final per-chunk contributions
    float sg_ = 0.f, sh_ = 0.f;
    #pragma unroll
    for (int nt = 0; nt < 4; nt++) {
        sg_ += d[nt][0] + d[nt][1];
        sh_ += d[nt][2] + d[nt][3];
    }
    sg_ += __shfl_xor_sync(0xffffffffu, sg_, 1);
    sg_ += __shfl_xor_sync(0xffffffffu, sg_, 2);
    sh_ += __shfl_xor_sync(0xffffffffu, sh_, 1);
    sh_ += __shfl_xor_sync(0xffffffffu, sh_, 2);

    const float LN2 = 0.69314718055994531f;
    float Dg = (float)(oe_g - oes_g) * LN2 + logf(sg_) - snl_g;
    float Dh = (float)(oe_h - oes_h) * LN2 + logf(sh_) - snl_h;
    if (c4 == 0) {
        g_part[b * NCH + ch_g] = Dg;
        g_part[b * NCH + ch_h] = Dh;
    }
}

// =====================================================================
// Kernel 3: deterministic reduction of 4096 chunk contributions
// =====================================================================
__global__ __launch_bounds__(256) void reduce_kernel(float* __restrict__ out) {
    __shared__ double ws[8];
    const int t = threadIdx.x;
    double v = 0.0;
    #pragma unroll
    for (int i = 0; i < 16; i++) v += (double)g_part[t * 16 + i];
    #pragma unroll
    for (int off = 16; off > 0; off >>= 1)
        v += __shfl_xor_sync(0xffffffffu, v, off);
    if ((t & 31) == 0) ws[t >> 5] = v;
    __syncthreads();
    if (t == 0) {
        double s = 0.0;
        #pragma unroll
        for (int i = 0; i < 8; i++) s += ws[i];
        out[0] = (float)s;
    }
}

extern "C" void kernel_launch(void* const* d_in, const int* in_sizes, int n_in,
                              void* d_out, int out_size) {
    const float* x     = (const float*)d_in[0];
    const int*   mask  = (const int*)d_in[1];
    const float* W     = (const float*)d_in[2];
    const float* trans = (const float*)d_in[3];

    emis_mma<<<(BATCH * TT) / 128, 128>>>(x, W);
    scan_mma<<<BATCH * 2, 32>>>(mask, trans);
    reduce_kernel<<<1, 256>>>((float*)d_out);
}